// round 1
// baseline (speedup 1.0000x reference)
#include <cuda_runtime.h>
#include <math.h>

// Problem constants
#define BSZ 4
#define SEQ 4096
#define EMB 1024
#define HD  64
#define ROWS (BSZ * SEQ)

// Scratch for Q, K, V projections (allocation-free: __device__ globals)
__device__ float g_q[ROWS * HD];
__device__ float g_k[ROWS * HD];
__device__ float g_v[ROWS * HD];

// ---------------------------------------------------------------------------
// Kernel 1: fused QKV projection.
//   out[r, 0:64]   = x[r,:] @ Wq   -> g_q
//   out[r, 64:128] = x[r,:] @ Wk   -> g_k
//   out[r,128:192] = x[r,:] @ Wv   -> g_v
// Tile: 64 rows x 192 cols per block, 256 threads, 4x12 register blocking,
// K-chunks of 32 staged through static shared memory (~34 KB).
// ---------------------------------------------------------------------------
#define PTM 64
#define PTK 32
#define PNC 192

__global__ __launch_bounds__(256) void qkv_kernel(
    const float* __restrict__ x,
    const float* __restrict__ Wq,
    const float* __restrict__ Wk,
    const float* __restrict__ Wv)
{
    __shared__ float xs[PTM][PTK + 4];   // 64 x 36 floats
    __shared__ float ws[PTK][PNC + 4];   // 32 x 196 floats

    const int tid = threadIdx.x;
    const int ty = tid >> 4;   // 0..15 : rows ty*4 .. ty*4+3
    const int tx = tid & 15;   // 0..15 : cols tx*12 .. tx*12+11
    const int r0 = blockIdx.x * PTM;

    float acc[4][12];
#pragma unroll
    for (int i = 0; i < 4; i++)
#pragma unroll
        for (int j = 0; j < 12; j++) acc[i][j] = 0.f;

    for (int k0 = 0; k0 < EMB; k0 += PTK) {
        __syncthreads();
        // Load x tile: 64 x 32 floats = 512 float4, 2 per thread
#pragma unroll
        for (int it = 0; it < 2; it++) {
            int f = tid + it * 256;
            int r = f >> 3;            // PTK/4 = 8 float4 per row
            int c4 = f & 7;
            *(float4*)&xs[r][c4 << 2] =
                *(const float4*)&x[(size_t)(r0 + r) * EMB + k0 + (c4 << 2)];
        }
        // Load W chunk: 3 matrices, each 32x64 floats = 512 float4, 2 per thread
        const float* Wmat[3] = {Wq, Wk, Wv};
#pragma unroll
        for (int mM = 0; mM < 3; mM++) {
            const float* W = Wmat[mM];
#pragma unroll
            for (int it = 0; it < 2; it++) {
                int f = tid + it * 256;
                int kk = f >> 4;       // 16 float4 per 64-col row
                int c4 = f & 15;
                *(float4*)&ws[kk][mM * 64 + (c4 << 2)] =
                    *(const float4*)&W[(size_t)(k0 + kk) * HD + (c4 << 2)];
            }
        }
        __syncthreads();

#pragma unroll 8
        for (int kk = 0; kk < PTK; kk++) {
            float xv0 = xs[ty * 4 + 0][kk];
            float xv1 = xs[ty * 4 + 1][kk];
            float xv2 = xs[ty * 4 + 2][kk];
            float xv3 = xs[ty * 4 + 3][kk];
            float4 w0 = *(const float4*)&ws[kk][tx * 12];
            float4 w1 = *(const float4*)&ws[kk][tx * 12 + 4];
            float4 w2 = *(const float4*)&ws[kk][tx * 12 + 8];
            float wv[12] = {w0.x, w0.y, w0.z, w0.w,
                            w1.x, w1.y, w1.z, w1.w,
                            w2.x, w2.y, w2.z, w2.w};
#pragma unroll
            for (int j = 0; j < 12; j++) {
                acc[0][j] = fmaf(xv0, wv[j], acc[0][j]);
                acc[1][j] = fmaf(xv1, wv[j], acc[1][j]);
                acc[2][j] = fmaf(xv2, wv[j], acc[2][j]);
                acc[3][j] = fmaf(xv3, wv[j], acc[3][j]);
            }
        }
    }

    // Epilogue: scatter into g_q / g_k / g_v
#pragma unroll
    for (int i = 0; i < 4; i++) {
        int row = r0 + ty * 4 + i;
#pragma unroll
        for (int j = 0; j < 12; j++) {
            int c = tx * 12 + j;
            float v = acc[i][j];
            if (c < 64)       g_q[(size_t)row * HD + c]         = v;
            else if (c < 128) g_k[(size_t)row * HD + (c - 64)]  = v;
            else              g_v[(size_t)row * HD + (c - 128)] = v;
        }
    }
}

// ---------------------------------------------------------------------------
// Kernel 2: causal flash attention (fp32), D=64.
// Block = (batch b, q-tile i of 64 rows), 256 threads, 4x4 reg tiles.
// smem tiles are 64x64 floats with an XOR swizzle on the float4 column:
//   phys_f4 = h4 ^ (row >> 2)
// -> conflict-free for all four access patterns (Q/K reads in QK^T,
//    P store, P/V reads in PV).
// ---------------------------------------------------------------------------
#define TILE_F (64 * 64)   // floats per tile

__device__ __forceinline__ int swz(int r, int h4) {
    return (r << 6) + (((h4) ^ (r >> 2)) << 2);
}

__global__ __launch_bounds__(256) void attn_kernel(float* __restrict__ out)
{
    extern __shared__ float sm[];
    float* Qs = sm;
    float* Ks = sm + TILE_F;
    float* Vs = sm + 2 * TILE_F;
    float* Ps = sm + 3 * TILE_F;

    const int b   = blockIdx.y;
    const int i   = (int)gridDim.x - 1 - (int)blockIdx.x;  // longest first
    const int tid = threadIdx.x;
    const int ty  = tid >> 4;   // row group: rows ty*4..ty*4+3
    const int tx  = tid & 15;   // col group: cols tx*4..tx*4+3
    const int qr0 = i * 64;

    const float* qg = g_q + (size_t)b * SEQ * HD;
    const float* kg = g_k + (size_t)b * SEQ * HD;
    const float* vg = g_v + (size_t)b * SEQ * HD;

    // Load Q tile (swizzled)
    for (int f = tid; f < 1024; f += 256) {
        int r = f >> 4, c4 = f & 15;
        *(float4*)&Qs[swz(r, c4)] =
            *(const float4*)&qg[(size_t)(qr0 + r) * HD + (c4 << 2)];
    }

    float m[4], l[4], acc[4][4];
#pragma unroll
    for (int rr = 0; rr < 4; rr++) {
        m[rr] = -1e30f; l[rr] = 0.f;
#pragma unroll
        for (int cc = 0; cc < 4; cc++) acc[rr][cc] = 0.f;
    }

    const float scale = 0.03125f;  // 1024^-0.5

    for (int j = 0; j <= i; j++) {
        __syncthreads();  // prior readers of Ks/Vs done (covers Qs 1st iter)
        const int kr0 = j * 64;
        for (int f = tid; f < 1024; f += 256) {
            int r = f >> 4, c4 = f & 15;
            int p = swz(r, c4);
            *(float4*)&Ks[p] = *(const float4*)&kg[(size_t)(kr0 + r) * HD + (c4 << 2)];
            *(float4*)&Vs[p] = *(const float4*)&vg[(size_t)(kr0 + r) * HD + (c4 << 2)];
        }
        __syncthreads();

        // ---- S = Q @ K^T (4x4 per thread) ----
        float s[4][4];
#pragma unroll
        for (int rr = 0; rr < 4; rr++)
#pragma unroll
            for (int cc = 0; cc < 4; cc++) s[rr][cc] = 0.f;

#pragma unroll 4
        for (int h4 = 0; h4 < 16; h4++) {
            float4 qv[4], kv[4];
#pragma unroll
            for (int rr = 0; rr < 4; rr++)
                qv[rr] = *(const float4*)&Qs[((ty * 4 + rr) << 6) + ((h4 ^ ty) << 2)];
#pragma unroll
            for (int cc = 0; cc < 4; cc++)
                kv[cc] = *(const float4*)&Ks[((tx * 4 + cc) << 6) + ((h4 ^ tx) << 2)];
#pragma unroll
            for (int rr = 0; rr < 4; rr++)
#pragma unroll
                for (int cc = 0; cc < 4; cc++) {
                    s[rr][cc] = fmaf(qv[rr].x, kv[cc].x, s[rr][cc]);
                    s[rr][cc] = fmaf(qv[rr].y, kv[cc].y, s[rr][cc]);
                    s[rr][cc] = fmaf(qv[rr].z, kv[cc].z, s[rr][cc]);
                    s[rr][cc] = fmaf(qv[rr].w, kv[cc].w, s[rr][cc]);
                }
        }

        // scale + causal mask (only diagonal tile can mask)
#pragma unroll
        for (int rr = 0; rr < 4; rr++)
#pragma unroll
            for (int cc = 0; cc < 4; cc++) s[rr][cc] *= scale;
        if (j == i) {
#pragma unroll
            for (int rr = 0; rr < 4; rr++)
#pragma unroll
                for (int cc = 0; cc < 4; cc++)
                    if (tx * 4 + cc > ty * 4 + rr) s[rr][cc] = -1e30f;
        }

        // ---- online softmax update + stage P into smem ----
#pragma unroll
        for (int rr = 0; rr < 4; rr++) {
            float mn = fmaxf(fmaxf(s[rr][0], s[rr][1]), fmaxf(s[rr][2], s[rr][3]));
#pragma unroll
            for (int off = 8; off; off >>= 1)
                mn = fmaxf(mn, __shfl_xor_sync(0xffffffffu, mn, off, 16));
            float mc = fmaxf(m[rr], mn);
            float alpha = __expf(m[rr] - mc);
            m[rr] = mc;
            float rs = 0.f;
#pragma unroll
            for (int cc = 0; cc < 4; cc++) {
                float pv = __expf(s[rr][cc] - mc);
                s[rr][cc] = pv;
                rs += pv;
            }
#pragma unroll
            for (int off = 8; off; off >>= 1)
                rs += __shfl_xor_sync(0xffffffffu, rs, off, 16);
            l[rr] = l[rr] * alpha + rs;
#pragma unroll
            for (int cc = 0; cc < 4; cc++) acc[rr][cc] *= alpha;

            float4 pv4 = make_float4(s[rr][0], s[rr][1], s[rr][2], s[rr][3]);
            *(float4*)&Ps[((ty * 4 + rr) << 6) + ((tx ^ ty) << 2)] = pv4;
        }
        __syncthreads();

        // ---- acc += P @ V ----
#pragma unroll 4
        for (int k4 = 0; k4 < 16; k4++) {
            float4 pv[4], vv[4];
#pragma unroll
            for (int rr = 0; rr < 4; rr++)
                pv[rr] = *(const float4*)&Ps[((ty * 4 + rr) << 6) + ((k4 ^ ty) << 2)];
#pragma unroll
            for (int kk = 0; kk < 4; kk++)
                vv[kk] = *(const float4*)&Vs[(((k4 << 2) + kk) << 6) + ((tx ^ k4) << 2)];
#pragma unroll
            for (int rr = 0; rr < 4; rr++) {
                acc[rr][0] = fmaf(pv[rr].x, vv[0].x, acc[rr][0]);
                acc[rr][0] = fmaf(pv[rr].y, vv[1].x, acc[rr][0]);
                acc[rr][0] = fmaf(pv[rr].z, vv[2].x, acc[rr][0]);
                acc[rr][0] = fmaf(pv[rr].w, vv[3].x, acc[rr][0]);
                acc[rr][1] = fmaf(pv[rr].x, vv[0].y, acc[rr][1]);
                acc[rr][1] = fmaf(pv[rr].y, vv[1].y, acc[rr][1]);
                acc[rr][1] = fmaf(pv[rr].z, vv[2].y, acc[rr][1]);
                acc[rr][1] = fmaf(pv[rr].w, vv[3].y, acc[rr][1]);
                acc[rr][2] = fmaf(pv[rr].x, vv[0].z, acc[rr][2]);
                acc[rr][2] = fmaf(pv[rr].y, vv[1].z, acc[rr][2]);
                acc[rr][2] = fmaf(pv[rr].z, vv[2].z, acc[rr][2]);
                acc[rr][2] = fmaf(pv[rr].w, vv[3].z, acc[rr][2]);
                acc[rr][3] = fmaf(pv[rr].x, vv[0].w, acc[rr][3]);
                acc[rr][3] = fmaf(pv[rr].y, vv[1].w, acc[rr][3]);
                acc[rr][3] = fmaf(pv[rr].z, vv[2].w, acc[rr][3]);
                acc[rr][3] = fmaf(pv[rr].w, vv[3].w, acc[rr][3]);
            }
        }
    }

    // Epilogue: normalize and store
#pragma unroll
    for (int rr = 0; rr < 4; rr++) {
        float inv = 1.f / l[rr];
        int row = qr0 + ty * 4 + rr;
        float4 o = make_float4(acc[rr][0] * inv, acc[rr][1] * inv,
                               acc[rr][2] * inv, acc[rr][3] * inv);
        *(float4*)&out[((size_t)b * SEQ + row) * HD + tx * 4] = o;
    }
}

// ---------------------------------------------------------------------------
// Launch: inputs in metadata order x, Wk, Wq, Wv. Output [B,S,H] fp32.
// ---------------------------------------------------------------------------
extern "C" void kernel_launch(void* const* d_in, const int* in_sizes, int n_in,
                              void* d_out, int out_size)
{
    const float* x  = (const float*)d_in[0];
    const float* Wk = (const float*)d_in[1];
    const float* Wq = (const float*)d_in[2];
    const float* Wv = (const float*)d_in[3];
    float* out = (float*)d_out;

    qkv_kernel<<<ROWS / PTM, 256>>>(x, Wq, Wk, Wv);

    const int smem = 4 * TILE_F * (int)sizeof(float);  // 64 KB
    cudaFuncSetAttribute(attn_kernel,
                         cudaFuncAttributeMaxDynamicSharedMemorySize, smem);
    attn_kernel<<<dim3(SEQ / 64, BSZ), 256, smem>>>(out);
}

// round 2
// speedup vs baseline: 1.2933x; 1.2933x over previous
#include <cuda_runtime.h>
#include <math.h>

// Problem constants
#define BSZ 4
#define SEQ 4096
#define EMB 1024
#define HD  64
#define ROWS (BSZ * SEQ)

// KV-split chunking: each attention CTA handles at most CH k-tiles.
#define CH 8
#define MAXSEG 8           // ceil(64 / CH)
#define SEG_PER_BATCH 288  // sum_{i=0}^{63} ceil((i+1)/8)

// Scratch (allocation-free: __device__ globals)
__device__ float g_q[ROWS * HD];
__device__ float g_k[ROWS * HD];
__device__ float g_v[ROWS * HD];
__device__ float g_pacc[(size_t)BSZ * MAXSEG * SEQ * HD];  // unnormalized partial out
__device__ float g_pm[BSZ * MAXSEG * SEQ];                 // partial max
__device__ float g_pl[BSZ * MAXSEG * SEQ];                 // partial sum

// ---------------------------------------------------------------------------
// cp.async helpers (global -> shared, 16B)
// ---------------------------------------------------------------------------
__device__ __forceinline__ void cp16(float* dst, const float* src) {
    unsigned int d = (unsigned int)__cvta_generic_to_shared(dst);
    asm volatile("cp.async.cg.shared.global [%0], [%1], 16;\n" :: "r"(d), "l"(src));
}
#define CP_COMMIT() asm volatile("cp.async.commit_group;\n" ::: "memory")
#define CP_WAIT0()  asm volatile("cp.async.wait_group 0;\n" ::: "memory")

// ---------------------------------------------------------------------------
// Kernel 1: fused QKV projection (unchanged — measured ~95% of FFMA floor).
// ---------------------------------------------------------------------------
#define PTM 64
#define PTK 32
#define PNC 192

__global__ __launch_bounds__(256) void qkv_kernel(
    const float* __restrict__ x,
    const float* __restrict__ Wq,
    const float* __restrict__ Wk,
    const float* __restrict__ Wv)
{
    __shared__ float xs[PTM][PTK + 4];
    __shared__ float ws[PTK][PNC + 4];

    const int tid = threadIdx.x;
    const int ty = tid >> 4;
    const int tx = tid & 15;
    const int r0 = blockIdx.x * PTM;

    float acc[4][12];
#pragma unroll
    for (int i = 0; i < 4; i++)
#pragma unroll
        for (int j = 0; j < 12; j++) acc[i][j] = 0.f;

    for (int k0 = 0; k0 < EMB; k0 += PTK) {
        __syncthreads();
#pragma unroll
        for (int it = 0; it < 2; it++) {
            int f = tid + it * 256;
            int r = f >> 3;
            int c4 = f & 7;
            *(float4*)&xs[r][c4 << 2] =
                *(const float4*)&x[(size_t)(r0 + r) * EMB + k0 + (c4 << 2)];
        }
        const float* Wmat[3] = {Wq, Wk, Wv};
#pragma unroll
        for (int mM = 0; mM < 3; mM++) {
            const float* W = Wmat[mM];
#pragma unroll
            for (int it = 0; it < 2; it++) {
                int f = tid + it * 256;
                int kk = f >> 4;
                int c4 = f & 15;
                *(float4*)&ws[kk][mM * 64 + (c4 << 2)] =
                    *(const float4*)&W[(size_t)(k0 + kk) * HD + (c4 << 2)];
            }
        }
        __syncthreads();

#pragma unroll 8
        for (int kk = 0; kk < PTK; kk++) {
            float xv0 = xs[ty * 4 + 0][kk];
            float xv1 = xs[ty * 4 + 1][kk];
            float xv2 = xs[ty * 4 + 2][kk];
            float xv3 = xs[ty * 4 + 3][kk];
            float4 w0 = *(const float4*)&ws[kk][tx * 12];
            float4 w1 = *(const float4*)&ws[kk][tx * 12 + 4];
            float4 w2 = *(const float4*)&ws[kk][tx * 12 + 8];
            float wv[12] = {w0.x, w0.y, w0.z, w0.w,
                            w1.x, w1.y, w1.z, w1.w,
                            w2.x, w2.y, w2.z, w2.w};
#pragma unroll
            for (int j = 0; j < 12; j++) {
                acc[0][j] = fmaf(xv0, wv[j], acc[0][j]);
                acc[1][j] = fmaf(xv1, wv[j], acc[1][j]);
                acc[2][j] = fmaf(xv2, wv[j], acc[2][j]);
                acc[3][j] = fmaf(xv3, wv[j], acc[3][j]);
            }
        }
    }

#pragma unroll
    for (int i = 0; i < 4; i++) {
        int row = r0 + ty * 4 + i;
#pragma unroll
        for (int j = 0; j < 12; j++) {
            int c = tx * 12 + j;
            float v = acc[i][j];
            if (c < 64)       g_q[(size_t)row * HD + c]         = v;
            else if (c < 128) g_k[(size_t)row * HD + (c - 64)]  = v;
            else              g_v[(size_t)row * HD + (c - 128)] = v;
        }
    }
}

// ---------------------------------------------------------------------------
// Kernel 2: causal flash attention segment (fp32), split-KV.
// Block = (batch b, flattened (q-tile i, segment s)). Each segment covers
// at most CH=8 k-tiles of 64 keys. Double-buffered K/V via cp.async.
// Partial (unnormalized acc, m, l) written to scratch; combine merges.
// ---------------------------------------------------------------------------
#define TILE_F (64 * 64)   // floats per tile

__device__ __forceinline__ int swz(int r, int h4) {
    return (r << 6) + (((h4) ^ (r >> 2)) << 2);
}

__global__ __launch_bounds__(256, 2) void attn_kernel()
{
    extern __shared__ float sm[];
    float* Qs = sm;
    float* Kb[2] = {sm + TILE_F,     sm + 3 * TILE_F};
    float* Vb[2] = {sm + 2 * TILE_F, sm + 4 * TILE_F};
    float* Ps = sm + 5 * TILE_F;

    const int b   = blockIdx.y;
    const int tid = threadIdx.x;
    const int ty  = tid >> 4;
    const int tx  = tid & 15;

    // Decode blockIdx.x -> (q-tile i, segment s), largest i first.
    int fid = blockIdx.x;
    int i = 0, s = 0;
    {
        int accn = 0;
        for (int t = 63; t >= 0; t--) {
            int c = (t + CH) >> 3;   // ceil((t+1)/CH)
            if (fid < accn + c) { i = t; s = fid - accn; break; }
            accn += c;
        }
    }
    const int T  = i + 1;            // causal tiles for this q-tile
    const int j0 = s * CH;
    const int j1 = (j0 + CH < T) ? (j0 + CH) : T;
    const int qr0 = i * 64;

    const float* qg = g_q + (size_t)b * SEQ * HD;
    const float* kg = g_k + (size_t)b * SEQ * HD;
    const float* vg = g_v + (size_t)b * SEQ * HD;

    // Prefetch first K/V tile into buffer 0
    {
        const int kr0 = j0 * 64;
        for (int f = tid; f < 1024; f += 256) {
            int r = f >> 4, c4 = f & 15;
            int p = swz(r, c4);
            cp16(&Kb[0][p], &kg[(size_t)(kr0 + r) * HD + (c4 << 2)]);
            cp16(&Vb[0][p], &vg[(size_t)(kr0 + r) * HD + (c4 << 2)]);
        }
    }
    CP_COMMIT();

    // Load Q tile (swizzled) with the 1/sqrt(E) scale folded in
    const float scale = 0.03125f;  // 1024^-0.5
    for (int f = tid; f < 1024; f += 256) {
        int r = f >> 4, c4 = f & 15;
        float4 q4 = *(const float4*)&qg[(size_t)(qr0 + r) * HD + (c4 << 2)];
        q4.x *= scale; q4.y *= scale; q4.z *= scale; q4.w *= scale;
        *(float4*)&Qs[swz(r, c4)] = q4;
    }

    float m[4], l[4], acc[4][4];
#pragma unroll
    for (int rr = 0; rr < 4; rr++) {
        m[rr] = -1e30f; l[rr] = 0.f;
#pragma unroll
        for (int cc = 0; cc < 4; cc++) acc[rr][cc] = 0.f;
    }

    int buf = 0;
    for (int j = j0; j < j1; j++) {
        CP_WAIT0();
        __syncthreads();

        // Prefetch next tile into the other buffer (overlaps compute)
        if (j + 1 < j1) {
            const int kr0 = (j + 1) * 64;
            float* Kn = Kb[buf ^ 1];
            float* Vn = Vb[buf ^ 1];
            for (int f = tid; f < 1024; f += 256) {
                int r = f >> 4, c4 = f & 15;
                int p = swz(r, c4);
                cp16(&Kn[p], &kg[(size_t)(kr0 + r) * HD + (c4 << 2)]);
                cp16(&Vn[p], &vg[(size_t)(kr0 + r) * HD + (c4 << 2)]);
            }
        }
        CP_COMMIT();

        const float* Ks = Kb[buf];
        const float* Vs = Vb[buf];

        // ---- S = Q @ K^T (4x4 per thread) ----
        float sreg[4][4];
#pragma unroll
        for (int rr = 0; rr < 4; rr++)
#pragma unroll
            for (int cc = 0; cc < 4; cc++) sreg[rr][cc] = 0.f;

#pragma unroll 4
        for (int h4 = 0; h4 < 16; h4++) {
            float4 qv[4], kv[4];
#pragma unroll
            for (int rr = 0; rr < 4; rr++)
                qv[rr] = *(const float4*)&Qs[((ty * 4 + rr) << 6) + ((h4 ^ ty) << 2)];
#pragma unroll
            for (int cc = 0; cc < 4; cc++)
                kv[cc] = *(const float4*)&Ks[((tx * 4 + cc) << 6) + ((h4 ^ tx) << 2)];
#pragma unroll
            for (int rr = 0; rr < 4; rr++)
#pragma unroll
                for (int cc = 0; cc < 4; cc++) {
                    sreg[rr][cc] = fmaf(qv[rr].x, kv[cc].x, sreg[rr][cc]);
                    sreg[rr][cc] = fmaf(qv[rr].y, kv[cc].y, sreg[rr][cc]);
                    sreg[rr][cc] = fmaf(qv[rr].z, kv[cc].z, sreg[rr][cc]);
                    sreg[rr][cc] = fmaf(qv[rr].w, kv[cc].w, sreg[rr][cc]);
                }
        }

        // causal mask (only the diagonal tile masks)
        if (j == i) {
#pragma unroll
            for (int rr = 0; rr < 4; rr++)
#pragma unroll
                for (int cc = 0; cc < 4; cc++)
                    if (tx * 4 + cc > ty * 4 + rr) sreg[rr][cc] = -1e30f;
        }

        // ---- online softmax update + stage P into smem ----
#pragma unroll
        for (int rr = 0; rr < 4; rr++) {
            float mn = fmaxf(fmaxf(sreg[rr][0], sreg[rr][1]),
                             fmaxf(sreg[rr][2], sreg[rr][3]));
#pragma unroll
            for (int off = 8; off; off >>= 1)
                mn = fmaxf(mn, __shfl_xor_sync(0xffffffffu, mn, off, 16));
            float mc = fmaxf(m[rr], mn);
            float alpha = __expf(m[rr] - mc);
            m[rr] = mc;
            float rs = 0.f;
#pragma unroll
            for (int cc = 0; cc < 4; cc++) {
                float pv = __expf(sreg[rr][cc] - mc);
                sreg[rr][cc] = pv;
                rs += pv;
            }
#pragma unroll
            for (int off = 8; off; off >>= 1)
                rs += __shfl_xor_sync(0xffffffffu, rs, off, 16);
            l[rr] = l[rr] * alpha + rs;
#pragma unroll
            for (int cc = 0; cc < 4; cc++) acc[rr][cc] *= alpha;

            float4 pv4 = make_float4(sreg[rr][0], sreg[rr][1], sreg[rr][2], sreg[rr][3]);
            *(float4*)&Ps[((ty * 4 + rr) << 6) + ((tx ^ ty) << 2)] = pv4;
        }
        __syncthreads();

        // ---- acc += P @ V ----
#pragma unroll 4
        for (int k4 = 0; k4 < 16; k4++) {
            float4 pv[4], vv[4];
#pragma unroll
            for (int rr = 0; rr < 4; rr++)
                pv[rr] = *(const float4*)&Ps[((ty * 4 + rr) << 6) + ((k4 ^ ty) << 2)];
#pragma unroll
            for (int kk = 0; kk < 4; kk++)
                vv[kk] = *(const float4*)&Vs[(((k4 << 2) + kk) << 6) + ((tx ^ k4) << 2)];
#pragma unroll
            for (int rr = 0; rr < 4; rr++) {
                acc[rr][0] = fmaf(pv[rr].x, vv[0].x, acc[rr][0]);
                acc[rr][0] = fmaf(pv[rr].y, vv[1].x, acc[rr][0]);
                acc[rr][0] = fmaf(pv[rr].z, vv[2].x, acc[rr][0]);
                acc[rr][0] = fmaf(pv[rr].w, vv[3].x, acc[rr][0]);
                acc[rr][1] = fmaf(pv[rr].x, vv[0].y, acc[rr][1]);
                acc[rr][1] = fmaf(pv[rr].y, vv[1].y, acc[rr][1]);
                acc[rr][1] = fmaf(pv[rr].z, vv[2].y, acc[rr][1]);
                acc[rr][1] = fmaf(pv[rr].w, vv[3].y, acc[rr][1]);
                acc[rr][2] = fmaf(pv[rr].x, vv[0].z, acc[rr][2]);
                acc[rr][2] = fmaf(pv[rr].y, vv[1].z, acc[rr][2]);
                acc[rr][2] = fmaf(pv[rr].z, vv[2].z, acc[rr][2]);
                acc[rr][2] = fmaf(pv[rr].w, vv[3].z, acc[rr][2]);
                acc[rr][3] = fmaf(pv[rr].x, vv[0].w, acc[rr][3]);
                acc[rr][3] = fmaf(pv[rr].y, vv[1].w, acc[rr][3]);
                acc[rr][3] = fmaf(pv[rr].z, vv[2].w, acc[rr][3]);
                acc[rr][3] = fmaf(pv[rr].w, vv[3].w, acc[rr][3]);
            }
        }
        buf ^= 1;
    }

    // Epilogue: write unnormalized partials + (m, l)
    const size_t segrow = ((size_t)b * MAXSEG + s) * SEQ + qr0;
#pragma unroll
    for (int rr = 0; rr < 4; rr++) {
        size_t row = segrow + ty * 4 + rr;
        float4 o = make_float4(acc[rr][0], acc[rr][1], acc[rr][2], acc[rr][3]);
        *(float4*)&g_pacc[row * HD + tx * 4] = o;
        if (tx == 0) {
            g_pm[row] = m[rr];
            g_pl[row] = l[rr];
        }
    }
}

// ---------------------------------------------------------------------------
// Kernel 3: combine split-KV partials and normalize.
// Block = 256 threads = 4 rows x 64 cols. Grid = (SEQ/4, B).
// ---------------------------------------------------------------------------
__global__ __launch_bounds__(256) void combine_kernel(float* __restrict__ out)
{
    const int b   = blockIdx.y;
    const int row = blockIdx.x * 4 + (threadIdx.x >> 6);
    const int col = threadIdx.x & 63;
    const int i   = row >> 6;
    const int nseg = (i + CH) >> 3;   // ceil((i+1)/CH)

    const size_t base = (size_t)b * MAXSEG * SEQ + row;

    float M = -1e30f;
#pragma unroll 4
    for (int s = 0; s < nseg; s++)
        M = fmaxf(M, g_pm[base + (size_t)s * SEQ]);

    float L = 0.f, a = 0.f;
#pragma unroll 4
    for (int s = 0; s < nseg; s++) {
        size_t idx = base + (size_t)s * SEQ;
        float w = __expf(g_pm[idx] - M);
        L = fmaf(w, g_pl[idx], L);
        a = fmaf(w, g_pacc[idx * HD + col], a);
    }

    out[((size_t)b * SEQ + row) * HD + col] = a / L;
}

// ---------------------------------------------------------------------------
// Launch: inputs in metadata order x, Wk, Wq, Wv. Output [B,S,H] fp32.
// ---------------------------------------------------------------------------
extern "C" void kernel_launch(void* const* d_in, const int* in_sizes, int n_in,
                              void* d_out, int out_size)
{
    const float* x  = (const float*)d_in[0];
    const float* Wk = (const float*)d_in[1];
    const float* Wq = (const float*)d_in[2];
    const float* Wv = (const float*)d_in[3];
    float* out = (float*)d_out;

    qkv_kernel<<<ROWS / PTM, 256>>>(x, Wq, Wk, Wv);

    const int smem = 6 * TILE_F * (int)sizeof(float);  // 96 KB
    cudaFuncSetAttribute(attn_kernel,
                         cudaFuncAttributeMaxDynamicSharedMemorySize, smem);
    attn_kernel<<<dim3(SEG_PER_BATCH, BSZ), 256, smem>>>();

    combine_kernel<<<dim3(SEQ / 4, BSZ), 256>>>(out);
}

// round 4
// speedup vs baseline: 3.4812x; 2.6918x over previous
#include <cuda_runtime.h>
#include <cuda_bf16.h>
#include <math.h>
#include <cstdint>

// Problem constants
#define BSZ 4
#define SEQ 4096
#define EMB 1024
#define HD  64
#define ROWS (BSZ * SEQ)

// KV-split chunking for attention
#define CH 8
#define MAXSEG 8
#define SEG_PER_BATCH 288

// Padded smem row stride: 72 bf16 = 144 bytes (conflict-free b32 frag loads,
// 16B-aligned rows for cp.async)
#define SSTR 144

// ---------------------------------------------------------------------------
// Scratch (allocation-free: __device__ globals)
// ---------------------------------------------------------------------------
__device__ __nv_bfloat16 g_qh[ROWS * HD];   // Q * 2^-5, bf16 hi
__device__ __nv_bfloat16 g_ql[ROWS * HD];   // residual lo
__device__ __nv_bfloat16 g_kh[ROWS * HD];
__device__ __nv_bfloat16 g_kl[ROWS * HD];
__device__ __nv_bfloat16 g_vth[(size_t)BSZ * HD * SEQ];  // V^T: [b][h][token]
__device__ __nv_bfloat16 g_vtl[(size_t)BSZ * HD * SEQ];
__device__ __nv_bfloat16 g_wth[192 * EMB];  // W^T hi: [n(Q|K|V)][k]
__device__ __nv_bfloat16 g_wtl[192 * EMB];
__device__ float g_pacc[(size_t)BSZ * MAXSEG * SEQ * HD];
__device__ float g_pm[BSZ * MAXSEG * SEQ];
__device__ float g_pl[BSZ * MAXSEG * SEQ];

// ---------------------------------------------------------------------------
// Helpers
// ---------------------------------------------------------------------------
__device__ __forceinline__ uint32_t smem_u32(const void* p) {
    uint32_t a;
    asm("{ .reg .u64 t; cvta.to.shared.u64 t, %1; cvt.u32.u64 %0, t; }"
        : "=r"(a) : "l"(p));
    return a;
}
__device__ __forceinline__ void cp16(uint32_t dst_s, const void* src) {
    asm volatile("cp.async.cg.shared.global [%0], [%1], 16;\n" :: "r"(dst_s), "l"(src));
}
#define CP_COMMIT() asm volatile("cp.async.commit_group;\n" ::: "memory")
#define CP_WAIT0()  asm volatile("cp.async.wait_group 0;\n" ::: "memory")

// m16n8k16 bf16 MMA, fp32 accumulate in-place
__device__ __forceinline__ void mma_bf16(float* d, const uint32_t* a, const uint32_t* b) {
    asm volatile(
        "mma.sync.aligned.m16n8k16.row.col.f32.bf16.bf16.f32 "
        "{%0,%1,%2,%3}, {%4,%5,%6,%7}, {%8,%9}, {%0,%1,%2,%3};\n"
        : "+f"(d[0]), "+f"(d[1]), "+f"(d[2]), "+f"(d[3])
        : "r"(a[0]), "r"(a[1]), "r"(a[2]), "r"(a[3]), "r"(b[0]), "r"(b[1]));
}

// Split two floats into packed bf16x2 hi + packed bf16x2 lo (x0 in low half)
__device__ __forceinline__ void split2(float x0, float x1, uint32_t& hi, uint32_t& lo) {
    __nv_bfloat16 h0 = __float2bfloat16(x0);
    __nv_bfloat16 h1 = __float2bfloat16(x1);
    __nv_bfloat162 hh = __halves2bfloat162(h0, h1);
    hi = *(uint32_t*)&hh;
    __nv_bfloat162 ll = __floats2bfloat162_rn(x0 - __bfloat162float(h0),
                                              x1 - __bfloat162float(h1));
    lo = *(uint32_t*)&ll;
}

// ---------------------------------------------------------------------------
// Kernel 0: W^T -> bf16 hi/lo split. [192][1024]
// ---------------------------------------------------------------------------
__global__ __launch_bounds__(256) void wprep_kernel(
    const float* __restrict__ Wq, const float* __restrict__ Wk,
    const float* __restrict__ Wv)
{
    const int n = blockIdx.x;            // 0..191
    const int m = n >> 6;
    const int h = n & 63;
    const float* W = (m == 0) ? Wq : (m == 1) ? Wk : Wv;
    for (int k = threadIdx.x; k < EMB; k += 256) {
        float v = W[(size_t)k * HD + h];
        __nv_bfloat16 hi = __float2bfloat16(v);
        g_wth[(size_t)n * EMB + k] = hi;
        g_wtl[(size_t)n * EMB + k] = __float2bfloat16(v - __bfloat162float(hi));
    }
}

// ---------------------------------------------------------------------------
// Kernel 1: QKV projection via split-bf16 mma.sync.
// CTA: 64 rows x 192 cols, 256 threads = 8 warps (4 row-groups x 2 col-groups).
// Warp tile: 16 x 96 (12 n-tiles of 8). K staged in chunks of 64.
// ---------------------------------------------------------------------------
#define XH_OFF 0
#define XL_OFF 9216
#define WH_OFF 18432
#define WL_OFF 46080
#define QKV_SM 73728

__global__ __launch_bounds__(256) void qkv_mma_kernel(const float* __restrict__ x)
{
    extern __shared__ char smc[];
    const uint32_t sb = smem_u32(smc);
    const int tid  = threadIdx.x;
    const int wid  = tid >> 5;
    const int lane = tid & 31;
    const int wr   = wid >> 1;      // row group 0..3 -> rows 16*wr
    const int wc   = wid & 1;       // col group 0..1 -> cols 96*wc
    const int r0   = blockIdx.x * 64;
    const int lq   = lane >> 2;     // 0..7
    const int lr   = lane & 3;      // 0..3

    float acc[12][4];
#pragma unroll
    for (int nt = 0; nt < 12; nt++)
#pragma unroll
        for (int q = 0; q < 4; q++) acc[nt][q] = 0.f;

    for (int c = 0; c < 16; c++) {
        const int k0 = c * 64;
        __syncthreads();   // previous chunk's consumers done

        // stage x chunk (fp32 -> bf16 hi/lo), 64 rows x 64 cols
#pragma unroll
        for (int it = 0; it < 2; it++) {
            int cid = tid + it * 256;        // 512 groups of 8 floats
            int row = cid >> 3, g = cid & 7;
            const float* src = x + (size_t)(r0 + row) * EMB + k0 + g * 8;
            float4 f0 = *(const float4*)src;
            float4 f1 = *(const float4*)(src + 4);
            uint32_t h[4], l[4];
            split2(f0.x, f0.y, h[0], l[0]);
            split2(f0.z, f0.w, h[1], l[1]);
            split2(f1.x, f1.y, h[2], l[2]);
            split2(f1.z, f1.w, h[3], l[3]);
            *(uint4*)(smc + XH_OFF + row * SSTR + g * 16) = *(uint4*)h;
            *(uint4*)(smc + XL_OFF + row * SSTR + g * 16) = *(uint4*)l;
        }
        // stage W^T chunk via cp.async: 192 rows x 64 cols, hi + lo
#pragma unroll
        for (int it = 0; it < 6; it++) {
            int cid = tid + it * 256;        // 1536 16B chunks per array
            int row = cid >> 3, g = cid & 7;
            size_t so = (size_t)row * EMB + k0 + g * 8;
            cp16(sb + WH_OFF + row * SSTR + g * 16, &g_wth[so]);
            cp16(sb + WL_OFF + row * SSTR + g * 16, &g_wtl[so]);
        }
        CP_COMMIT();
        CP_WAIT0();
        __syncthreads();

        // 4 k16 steps
#pragma unroll
        for (int ks = 0; ks < 4; ks++) {
            const int koff = ks * 32 + lr * 4;   // byte offset in row
            const int rowA = wr * 16 + lq;
            uint32_t aH[4], aL[4];
            aH[0] = *(const uint32_t*)(smc + XH_OFF + rowA * SSTR + koff);
            aH[1] = *(const uint32_t*)(smc + XH_OFF + (rowA + 8) * SSTR + koff);
            aH[2] = *(const uint32_t*)(smc + XH_OFF + rowA * SSTR + koff + 16);
            aH[3] = *(const uint32_t*)(smc + XH_OFF + (rowA + 8) * SSTR + koff + 16);
            aL[0] = *(const uint32_t*)(smc + XL_OFF + rowA * SSTR + koff);
            aL[1] = *(const uint32_t*)(smc + XL_OFF + (rowA + 8) * SSTR + koff);
            aL[2] = *(const uint32_t*)(smc + XL_OFF + rowA * SSTR + koff + 16);
            aL[3] = *(const uint32_t*)(smc + XL_OFF + (rowA + 8) * SSTR + koff + 16);
#pragma unroll
            for (int nt = 0; nt < 12; nt++) {
                int n = wc * 96 + nt * 8 + lq;
                const char* bp = smc + WH_OFF + n * SSTR + koff;
                const char* bq = smc + WL_OFF + n * SSTR + koff;
                uint32_t bH[2] = {*(const uint32_t*)bp, *(const uint32_t*)(bp + 16)};
                uint32_t bL[2] = {*(const uint32_t*)bq, *(const uint32_t*)(bq + 16)};
                mma_bf16(acc[nt], aH, bH);
                mma_bf16(acc[nt], aH, bL);
                mma_bf16(acc[nt], aL, bH);
            }
        }
    }

    // Epilogue: emit Q (scaled, split), K (split), V^T (split)
    const int rbase = r0 + wr * 16 + lq;
    const float scale = 0.03125f;  // 1024^-0.5, exact power of 2
#pragma unroll
    for (int nt = 0; nt < 12; nt++) {
        int cc = wc * 96 + nt * 8 + lr * 2;
#pragma unroll
        for (int hh = 0; hh < 2; hh++) {
            int row = rbase + 8 * hh;
            float v0 = acc[nt][2 * hh], v1 = acc[nt][2 * hh + 1];
            if (cc < 64) {
                uint32_t hi, lo;
                split2(v0 * scale, v1 * scale, hi, lo);
                *(uint32_t*)&g_qh[(size_t)row * HD + cc] = hi;
                *(uint32_t*)&g_ql[(size_t)row * HD + cc] = lo;
            } else if (cc < 128) {
                uint32_t hi, lo;
                split2(v0, v1, hi, lo);
                *(uint32_t*)&g_kh[(size_t)row * HD + cc - 64] = hi;
                *(uint32_t*)&g_kl[(size_t)row * HD + cc - 64] = lo;
            } else {
                int h = cc - 128;
                int b = row >> 12;          // /SEQ
                int tok = row & (SEQ - 1);
                size_t base = (size_t)b * HD * SEQ + tok;
                __nv_bfloat16 h0 = __float2bfloat16(v0);
                __nv_bfloat16 h1 = __float2bfloat16(v1);
                g_vth[base + (size_t)h * SEQ]       = h0;
                g_vth[base + (size_t)(h + 1) * SEQ] = h1;
                g_vtl[base + (size_t)h * SEQ]       = __float2bfloat16(v0 - __bfloat162float(h0));
                g_vtl[base + (size_t)(h + 1) * SEQ] = __float2bfloat16(v1 - __bfloat162float(h1));
            }
        }
    }
}

// ---------------------------------------------------------------------------
// Kernel 2: causal flash attention, split-KV, split-bf16 mma.sync.
// CTA = 128 threads (4 warps), q-tile 64 rows (16/warp), k-tiles of 64 keys.
// ---------------------------------------------------------------------------
#define QH_OFF 0
#define QL_OFF 9216
#define KH_OFF(b) (18432 + (b) * 36864)
#define KL_OFF(b) (27648 + (b) * 36864)
#define VH_OFF(b) (36864 + (b) * 36864)
#define VL_OFF(b) (46080 + (b) * 36864)
#define ATTN_SM 92160

__global__ __launch_bounds__(128) void attn_kernel()
{
    extern __shared__ char smc[];
    const uint32_t sb = smem_u32(smc);
    const int tid  = threadIdx.x;
    const int w    = tid >> 5;
    const int lane = tid & 31;
    const int lq   = lane >> 2;
    const int lr   = lane & 3;
    const int b    = blockIdx.y;

    // decode blockIdx.x -> (q-tile i, segment s)
    int fid = blockIdx.x;
    int i = 0, s = 0;
    {
        int accn = 0;
        for (int t = 63; t >= 0; t--) {
            int c = (t + CH) >> 3;
            if (fid < accn + c) { i = t; s = fid - accn; break; }
            accn += c;
        }
    }
    const int T  = i + 1;
    const int j0 = s * CH;
    const int j1 = (j0 + CH < T) ? (j0 + CH) : T;
    const int qr0 = i * 64;

    const size_t tok0  = (size_t)b * SEQ;           // row base in g_qh/g_kh
    const size_t vbase = (size_t)b * HD * SEQ;      // base in g_vth

    // stage Q (hi/lo) + first K/V tile
    {
        int kr0 = j0 * 64;
#pragma unroll
        for (int it = 0; it < 4; it++) {
            int cid = tid + it * 128;   // 512: 64 rows x 8 chunks
            int row = cid >> 3, g = cid & 7;
            cp16(sb + QH_OFF + row * SSTR + g * 16, &g_qh[(tok0 + qr0 + row) * HD + g * 8]);
            cp16(sb + QL_OFF + row * SSTR + g * 16, &g_ql[(tok0 + qr0 + row) * HD + g * 8]);
            cp16(sb + KH_OFF(0) + row * SSTR + g * 16, &g_kh[(tok0 + kr0 + row) * HD + g * 8]);
            cp16(sb + KL_OFF(0) + row * SSTR + g * 16, &g_kl[(tok0 + kr0 + row) * HD + g * 8]);
            cp16(sb + VH_OFF(0) + row * SSTR + g * 16, &g_vth[vbase + (size_t)row * SEQ + kr0 + g * 8]);
            cp16(sb + VL_OFF(0) + row * SSTR + g * 16, &g_vtl[vbase + (size_t)row * SEQ + kr0 + g * 8]);
        }
    }
    CP_COMMIT();

    float O[8][4];
#pragma unroll
    for (int nt = 0; nt < 8; nt++)
#pragma unroll
        for (int q = 0; q < 4; q++) O[nt][q] = 0.f;
    float m0 = -1e30f, m1 = -1e30f, l0 = 0.f, l1 = 0.f;

    int buf = 0;
    for (int j = j0; j < j1; j++) {
        CP_WAIT0();
        __syncthreads();

        // prefetch next tile
        if (j + 1 < j1) {
            int kr0 = (j + 1) * 64;
            int nb = buf ^ 1;
#pragma unroll
            for (int it = 0; it < 4; it++) {
                int cid = tid + it * 128;
                int row = cid >> 3, g = cid & 7;
                cp16(sb + KH_OFF(nb) + row * SSTR + g * 16, &g_kh[(tok0 + kr0 + row) * HD + g * 8]);
                cp16(sb + KL_OFF(nb) + row * SSTR + g * 16, &g_kl[(tok0 + kr0 + row) * HD + g * 8]);
                cp16(sb + VH_OFF(nb) + row * SSTR + g * 16, &g_vth[vbase + (size_t)row * SEQ + kr0 + g * 8]);
                cp16(sb + VL_OFF(nb) + row * SSTR + g * 16, &g_vtl[vbase + (size_t)row * SEQ + kr0 + g * 8]);
            }
        }
        CP_COMMIT();

        const char* Kh = smc + KH_OFF(buf);
        const char* Kl = smc + KL_OFF(buf);
        const char* Vh = smc + VH_OFF(buf);
        const char* Vl = smc + VL_OFF(buf);

        // ---- S = Q K^T ----
        float S[8][4];
#pragma unroll
        for (int nt = 0; nt < 8; nt++)
#pragma unroll
            for (int q = 0; q < 4; q++) S[nt][q] = 0.f;

#pragma unroll
        for (int kf = 0; kf < 4; kf++) {
            const int koff = kf * 32 + lr * 4;
            const int rowA = w * 16 + lq;
            uint32_t aH[4], aL[4];
            aH[0] = *(const uint32_t*)(smc + QH_OFF + rowA * SSTR + koff);
            aH[1] = *(const uint32_t*)(smc + QH_OFF + (rowA + 8) * SSTR + koff);
            aH[2] = *(const uint32_t*)(smc + QH_OFF + rowA * SSTR + koff + 16);
            aH[3] = *(const uint32_t*)(smc + QH_OFF + (rowA + 8) * SSTR + koff + 16);
            aL[0] = *(const uint32_t*)(smc + QL_OFF + rowA * SSTR + koff);
            aL[1] = *(const uint32_t*)(smc + QL_OFF + (rowA + 8) * SSTR + koff);
            aL[2] = *(const uint32_t*)(smc + QL_OFF + rowA * SSTR + koff + 16);
            aL[3] = *(const uint32_t*)(smc + QL_OFF + (rowA + 8) * SSTR + koff + 16);
#pragma unroll
            for (int nt = 0; nt < 8; nt++) {
                int key = nt * 8 + lq;
                const char* bp = Kh + key * SSTR + koff;
                const char* bq = Kl + key * SSTR + koff;
                uint32_t bH[2] = {*(const uint32_t*)bp, *(const uint32_t*)(bp + 16)};
                uint32_t bL[2] = {*(const uint32_t*)bq, *(const uint32_t*)(bq + 16)};
                mma_bf16(S[nt], aH, bH);
                mma_bf16(S[nt], aH, bL);
                mma_bf16(S[nt], aL, bH);
            }
        }

        // causal mask (diagonal tile only)
        if (j == i) {
            int r0g = w * 16 + lq;
#pragma unroll
            for (int nt = 0; nt < 8; nt++) {
                int c0 = nt * 8 + lr * 2;
                if (c0 > r0g)         S[nt][0] = -1e30f;
                if (c0 + 1 > r0g)     S[nt][1] = -1e30f;
                if (c0 > r0g + 8)     S[nt][2] = -1e30f;
                if (c0 + 1 > r0g + 8) S[nt][3] = -1e30f;
            }
        }

        // ---- online softmax ----
        float mn0 = -1e30f, mn1 = -1e30f;
#pragma unroll
        for (int nt = 0; nt < 8; nt++) {
            mn0 = fmaxf(mn0, fmaxf(S[nt][0], S[nt][1]));
            mn1 = fmaxf(mn1, fmaxf(S[nt][2], S[nt][3]));
        }
        mn0 = fmaxf(mn0, __shfl_xor_sync(0xffffffffu, mn0, 1));
        mn0 = fmaxf(mn0, __shfl_xor_sync(0xffffffffu, mn0, 2));
        mn1 = fmaxf(mn1, __shfl_xor_sync(0xffffffffu, mn1, 1));
        mn1 = fmaxf(mn1, __shfl_xor_sync(0xffffffffu, mn1, 2));
        float mc0 = fmaxf(m0, mn0), mc1 = fmaxf(m1, mn1);
        float al0 = __expf(m0 - mc0), al1 = __expf(m1 - mc1);
        m0 = mc0; m1 = mc1;
        float rs0 = 0.f, rs1 = 0.f;
#pragma unroll
        for (int nt = 0; nt < 8; nt++) {
            S[nt][0] = __expf(S[nt][0] - mc0);
            S[nt][1] = __expf(S[nt][1] - mc0);
            S[nt][2] = __expf(S[nt][2] - mc1);
            S[nt][3] = __expf(S[nt][3] - mc1);
            rs0 += S[nt][0] + S[nt][1];
            rs1 += S[nt][2] + S[nt][3];
        }
        rs0 += __shfl_xor_sync(0xffffffffu, rs0, 1);
        rs0 += __shfl_xor_sync(0xffffffffu, rs0, 2);
        rs1 += __shfl_xor_sync(0xffffffffu, rs1, 1);
        rs1 += __shfl_xor_sync(0xffffffffu, rs1, 2);
        l0 = l0 * al0 + rs0;
        l1 = l1 * al1 + rs1;
#pragma unroll
        for (int nt = 0; nt < 8; nt++) {
            O[nt][0] *= al0; O[nt][1] *= al0;
            O[nt][2] *= al1; O[nt][3] *= al1;
        }

        // ---- O += P V (P re-packed from S frags, split hi/lo) ----
#pragma unroll
        for (int kf = 0; kf < 4; kf++) {
            uint32_t aPh[4], aPl[4];
            split2(S[2 * kf][0],     S[2 * kf][1],     aPh[0], aPl[0]);
            split2(S[2 * kf][2],     S[2 * kf][3],     aPh[1], aPl[1]);
            split2(S[2 * kf + 1][0], S[2 * kf + 1][1], aPh[2], aPl[2]);
            split2(S[2 * kf + 1][2], S[2 * kf + 1][3], aPh[3], aPl[3]);
            const int koff = kf * 32 + lr * 4;
#pragma unroll
            for (int nt = 0; nt < 8; nt++) {
                int h = nt * 8 + lq;
                const char* bp = Vh + h * SSTR + koff;
                const char* bq = Vl + h * SSTR + koff;
                uint32_t bH[2] = {*(const uint32_t*)bp, *(const uint32_t*)(bp + 16)};
                uint32_t bL[2] = {*(const uint32_t*)bq, *(const uint32_t*)(bq + 16)};
                mma_bf16(O[nt], aPh, bH);
                mma_bf16(O[nt], aPh, bL);
                mma_bf16(O[nt], aPl, bH);
            }
        }
        buf ^= 1;
    }

    // Epilogue: unnormalized partials + (m, l)
    const size_t segrow = ((size_t)b * MAXSEG + s) * SEQ + qr0 + w * 16 + lq;
#pragma unroll
    for (int nt = 0; nt < 8; nt++) {
        int cc = nt * 8 + lr * 2;
        *(float2*)&g_pacc[segrow * HD + cc] = make_float2(O[nt][0], O[nt][1]);
        *(float2*)&g_pacc[(segrow + 8) * HD + cc] = make_float2(O[nt][2], O[nt][3]);
    }
    if (lr == 0) {
        g_pm[segrow] = m0;     g_pl[segrow] = l0;
        g_pm[segrow + 8] = m1; g_pl[segrow + 8] = l1;
    }
}

// ---------------------------------------------------------------------------
// Kernel 3: combine split-KV partials and normalize.
// ---------------------------------------------------------------------------
__global__ __launch_bounds__(256) void combine_kernel(float* __restrict__ out)
{
    const int b   = blockIdx.y;
    const int row = blockIdx.x * 4 + (threadIdx.x >> 6);
    const int col = threadIdx.x & 63;
    const int i   = row >> 6;
    const int nseg = (i + CH) >> 3;

    const size_t base = (size_t)b * MAXSEG * SEQ + row;

    float M = -1e30f;
#pragma unroll 4
    for (int s = 0; s < nseg; s++)
        M = fmaxf(M, g_pm[base + (size_t)s * SEQ]);

    float L = 0.f, a = 0.f;
#pragma unroll 4
    for (int s = 0; s < nseg; s++) {
        size_t idx = base + (size_t)s * SEQ;
        float w = __expf(g_pm[idx] - M);
        L = fmaf(w, g_pl[idx], L);
        a = fmaf(w, g_pacc[idx * HD + col], a);
    }

    out[((size_t)b * SEQ + row) * HD + col] = a / L;
}

// ---------------------------------------------------------------------------
// Launch: inputs in metadata order x, Wk, Wq, Wv. Output [B,S,H] fp32.
// ---------------------------------------------------------------------------
extern "C" void kernel_launch(void* const* d_in, const int* in_sizes, int n_in,
                              void* d_out, int out_size)
{
    const float* x  = (const float*)d_in[0];
    const float* Wk = (const float*)d_in[1];
    const float* Wq = (const float*)d_in[2];
    const float* Wv = (const float*)d_in[3];
    float* out = (float*)d_out;

    wprep_kernel<<<192, 256>>>(Wq, Wk, Wv);

    cudaFuncSetAttribute(qkv_mma_kernel,
                         cudaFuncAttributeMaxDynamicSharedMemorySize, QKV_SM);
    qkv_mma_kernel<<<ROWS / 64, 256, QKV_SM>>>(x);

    cudaFuncSetAttribute(attn_kernel,
                         cudaFuncAttributeMaxDynamicSharedMemorySize, ATTN_SM);
    attn_kernel<<<dim3(SEG_PER_BATCH, BSZ), 128, ATTN_SM>>>();

    combine_kernel<<<dim3(SEQ / 4, BSZ), 256>>>(out);
}